// round 1
// baseline (speedup 1.0000x reference)
#include <cuda_runtime.h>
#include <math.h>

#define LNUM 6
#define DMOD 768
#define HNUM 12
#define DKH  64
#define FFD  3072
#define VOC  50257
#define SEQ  1024
#define BAT  2
#define MTOK (BAT*SEQ)   // 2048

// ---------------- device scratch (no allocations allowed) ----------------
__device__ float g_x  [MTOK*DMOD];
__device__ float g_h  [MTOK*DMOD];
__device__ float g_q  [MTOK*DMOD];
__device__ float g_k  [MTOK*DMOD];
__device__ float g_v  [MTOK*DMOD];
__device__ float g_att[MTOK*DMOD];
__device__ float g_ff [MTOK*FFD];

// ---------------- embedding + positional encoding ----------------
__global__ void embed_kernel(const int* __restrict__ ids,
                             const float* __restrict__ emb,
                             const float* __restrict__ pe,
                             float* __restrict__ X) {
    int i = blockIdx.x * blockDim.x + threadIdx.x;
    if (i >= MTOK * DMOD) return;
    int d = i % DMOD;
    int t = i / DMOD;
    int s = t % SEQ;
    X[i] = emb[(size_t)ids[t] * DMOD + d] + pe[s * DMOD + d];
}

// ---------------- layernorm: one block per row ----------------
__global__ void ln_kernel(const float* __restrict__ X,
                          const float* __restrict__ w,
                          const float* __restrict__ bvec,
                          float* __restrict__ Y) {
    __shared__ float red[256];
    int row = blockIdx.x;
    int tid = threadIdx.x;
    const float* x = X + (size_t)row * DMOD;

    float s = 0.f;
    for (int i = tid; i < DMOD; i += 256) s += x[i];
    red[tid] = s; __syncthreads();
    for (int o = 128; o > 0; o >>= 1) { if (tid < o) red[tid] += red[tid + o]; __syncthreads(); }
    float mu = red[0] * (1.0f / DMOD);
    __syncthreads();

    float v = 0.f;
    for (int i = tid; i < DMOD; i += 256) { float t = x[i] - mu; v += t * t; }
    red[tid] = v; __syncthreads();
    for (int o = 128; o > 0; o >>= 1) { if (tid < o) red[tid] += red[tid + o]; __syncthreads(); }
    float rstd = rsqrtf(red[0] * (1.0f / DMOD) + 1e-5f);

    float* y = Y + (size_t)row * DMOD;
    for (int i = tid; i < DMOD; i += 256)
        y[i] = (x[i] - mu) * rstd * w[i] + bvec[i];
}

// ---------------- tiled GEMM: C[M,N] = A[M,K] @ B[K,N]  (+epilogue) ----------------
// EP bits: 1=bias, 2=gelu, 4=residual add
#define EP_BIAS 1
#define EP_GELU 2
#define EP_RES  4

__device__ __forceinline__ float gelu_exact(float x) {
    return 0.5f * x * (1.0f + erff(x * 0.70710678118654752f));
}

template<int EP>
__global__ __launch_bounds__(256)
void gemm_nn(const float* __restrict__ A, const float* __restrict__ Bm,
             const float* __restrict__ bias, const float* __restrict__ res,
             float* __restrict__ C, int M, int N, int K) {
    __shared__ float As[16][68];
    __shared__ float Bs[16][68];
    int tid = threadIdx.x;
    int tx = tid % 16, ty = tid / 16;
    int bm = blockIdx.y * 64, bn = blockIdx.x * 64;

    float acc[4][4] = {};

    int am  = tid >> 2;          // 0..63
    int ak  = (tid & 3) * 4;     // 0,4,8,12
    int bk  = tid >> 4;          // 0..15
    int bn4 = (tid & 15) * 4;    // 0..60

    const float* Aptr = A + (size_t)(bm + am) * K + ak;
    const float* Bptr = Bm + (size_t)bk * N + bn + bn4;

    for (int k0 = 0; k0 < K; k0 += 16) {
        float4 av = *reinterpret_cast<const float4*>(Aptr + k0);
        As[ak + 0][am] = av.x; As[ak + 1][am] = av.y;
        As[ak + 2][am] = av.z; As[ak + 3][am] = av.w;
        float4 bv = *reinterpret_cast<const float4*>(Bptr + (size_t)k0 * N);
        *reinterpret_cast<float4*>(&Bs[bk][bn4]) = bv;
        __syncthreads();
        #pragma unroll
        for (int kk = 0; kk < 16; kk++) {
            float4 a = *reinterpret_cast<const float4*>(&As[kk][ty * 4]);
            float4 b = *reinterpret_cast<const float4*>(&Bs[kk][tx * 4]);
            acc[0][0] += a.x*b.x; acc[0][1] += a.x*b.y; acc[0][2] += a.x*b.z; acc[0][3] += a.x*b.w;
            acc[1][0] += a.y*b.x; acc[1][1] += a.y*b.y; acc[1][2] += a.y*b.z; acc[1][3] += a.y*b.w;
            acc[2][0] += a.z*b.x; acc[2][1] += a.z*b.y; acc[2][2] += a.z*b.z; acc[2][3] += a.z*b.w;
            acc[3][0] += a.w*b.x; acc[3][1] += a.w*b.y; acc[3][2] += a.w*b.z; acc[3][3] += a.w*b.w;
        }
        __syncthreads();
    }

    #pragma unroll
    for (int i = 0; i < 4; i++) {
        int m = bm + ty * 4 + i;
        #pragma unroll
        for (int j = 0; j < 4; j++) {
            int n = bn + tx * 4 + j;
            float v = acc[i][j];
            if (EP & EP_BIAS) v += bias[n];
            if (EP & EP_GELU) v = gelu_exact(v);
            if (EP & EP_RES)  v += res[(size_t)m * N + n];
            C[(size_t)m * N + n] = v;
        }
    }
}

// ---------------- tiled GEMM NT: C[M,N] = A[M,K] @ B[N,K]^T  (lm_head) ----------------
__global__ __launch_bounds__(256)
void gemm_nt(const float* __restrict__ A, const float* __restrict__ Bm,
             float* __restrict__ C, int M, int N, int K) {
    __shared__ float As[16][68];
    __shared__ float Bs[16][68];
    int tid = threadIdx.x;
    int tx = tid % 16, ty = tid / 16;
    int bm = blockIdx.y * 64, bn = blockIdx.x * 64;

    float acc[4][4] = {};

    int am = tid >> 2;
    int ak = (tid & 3) * 4;
    int bnrow = tid >> 2;        // 0..63 : n within tile
    int bkk   = (tid & 3) * 4;   // 0,4,8,12

    const float* Aptr = A + (size_t)(bm + am) * K + ak;
    bool nvalid = (bn + bnrow) < N;
    const float* Bptr = Bm + (size_t)(nvalid ? (bn + bnrow) : 0) * K + bkk;

    for (int k0 = 0; k0 < K; k0 += 16) {
        float4 av = *reinterpret_cast<const float4*>(Aptr + k0);
        As[ak + 0][am] = av.x; As[ak + 1][am] = av.y;
        As[ak + 2][am] = av.z; As[ak + 3][am] = av.w;
        float4 bv = make_float4(0.f, 0.f, 0.f, 0.f);
        if (nvalid) bv = *reinterpret_cast<const float4*>(Bptr + k0);
        Bs[bkk + 0][bnrow] = bv.x; Bs[bkk + 1][bnrow] = bv.y;
        Bs[bkk + 2][bnrow] = bv.z; Bs[bkk + 3][bnrow] = bv.w;
        __syncthreads();
        #pragma unroll
        for (int kk = 0; kk < 16; kk++) {
            float4 a = *reinterpret_cast<const float4*>(&As[kk][ty * 4]);
            float4 b = *reinterpret_cast<const float4*>(&Bs[kk][tx * 4]);
            acc[0][0] += a.x*b.x; acc[0][1] += a.x*b.y; acc[0][2] += a.x*b.z; acc[0][3] += a.x*b.w;
            acc[1][0] += a.y*b.x; acc[1][1] += a.y*b.y; acc[1][2] += a.y*b.z; acc[1][3] += a.y*b.w;
            acc[2][0] += a.z*b.x; acc[2][1] += a.z*b.y; acc[2][2] += a.z*b.z; acc[2][3] += a.z*b.w;
            acc[3][0] += a.w*b.x; acc[3][1] += a.w*b.y; acc[3][2] += a.w*b.z; acc[3][3] += a.w*b.w;
        }
        __syncthreads();
    }

    #pragma unroll
    for (int i = 0; i < 4; i++) {
        int m = bm + ty * 4 + i;
        #pragma unroll
        for (int j = 0; j < 4; j++) {
            int n = bn + tx * 4 + j;
            if (n < N) C[(size_t)m * N + n] = acc[i][j];
        }
    }
}

// ---------------- attention: one block per (b, h, query-row) ----------------
__global__ __launch_bounds__(128)
void attn_kernel(const float* __restrict__ Q, const float* __restrict__ Kk,
                 const float* __restrict__ Vv, const int* __restrict__ amask,
                 float* __restrict__ O) {
    __shared__ float sc[SEQ];
    __shared__ float qrow[DKH];
    __shared__ float red[128];
    int b = blockIdx.z, h = blockIdx.y, qi = blockIdx.x;
    int tid = threadIdx.x;
    int len = qi + 1;                       // causal
    const float scale = 0.125f;             // 1/sqrt(64)
    int qbase = ((b * SEQ + qi) * DMOD + h * DKH);

    if (tid < DKH) qrow[tid] = Q[qbase + tid];
    __syncthreads();

    // pass 1: scores + running max
    float lmax = -INFINITY;
    for (int kk = tid; kk < len; kk += 128) {
        const float4* kp = reinterpret_cast<const float4*>(Kk + ((b * SEQ + kk) * DMOD + h * DKH));
        float dot = 0.f;
        #pragma unroll
        for (int i = 0; i < 16; i++) {
            float4 kv = kp[i];
            float4 qv = reinterpret_cast<const float4*>(qrow)[i];
            dot += kv.x*qv.x + kv.y*qv.y + kv.z*qv.z + kv.w*qv.w;
        }
        float s = dot * scale;
        if (amask[b * SEQ + kk] == 0) s = -1e9f;
        sc[kk] = s;
        lmax = fmaxf(lmax, s);
    }
    red[tid] = lmax; __syncthreads();
    for (int o = 64; o > 0; o >>= 1) { if (tid < o) red[tid] = fmaxf(red[tid], red[tid + o]); __syncthreads(); }
    float mx = red[0];
    __syncthreads();

    // exp + sum
    float lsum = 0.f;
    for (int kk = tid; kk < len; kk += 128) {
        float e = expf(sc[kk] - mx);
        sc[kk] = e;
        lsum += e;
    }
    red[tid] = lsum; __syncthreads();
    for (int o = 64; o > 0; o >>= 1) { if (tid < o) red[tid] += red[tid + o]; __syncthreads(); }
    float inv = 1.0f / red[0];
    __syncthreads();

    // pass 2: O = P @ V   (threads: d = tid&63, two key-halves)
    int d = tid & 63, half = tid >> 6;
    float acc = 0.f;
    for (int kk = half; kk < len; kk += 2)
        acc += sc[kk] * Vv[((b * SEQ + kk) * DMOD + h * DKH) + d];
    red[tid] = acc; __syncthreads();
    if (half == 0)
        O[qbase + d] = (red[d] + red[d + 64]) * inv;
}

// ---------------- launch sequence ----------------
extern "C" void kernel_launch(void* const* d_in, const int* in_sizes, int n_in,
                              void* d_out, int out_size) {
    const int*   ids   = (const int*)  d_in[0];
    const int*   amask = (const int*)  d_in[1];
    const float* emb   = (const float*)d_in[2];
    const float* pe    = (const float*)d_in[3];
    const float* wq    = (const float*)d_in[4];
    const float* wk    = (const float*)d_in[5];
    const float* wv    = (const float*)d_in[6];
    const float* wo    = (const float*)d_in[7];
    const float* ln1w  = (const float*)d_in[8];
    const float* ln1b  = (const float*)d_in[9];
    const float* ln2w  = (const float*)d_in[10];
    const float* ln2b  = (const float*)d_in[11];
    const float* w1    = (const float*)d_in[12];
    const float* b1    = (const float*)d_in[13];
    const float* w2    = (const float*)d_in[14];
    const float* b2    = (const float*)d_in[15];
    const float* lnfw  = (const float*)d_in[16];
    const float* lnfb  = (const float*)d_in[17];
    float* out = (float*)d_out;

    float *x, *h, *q, *k, *v, *att, *ff;
    cudaGetSymbolAddress((void**)&x,   g_x);
    cudaGetSymbolAddress((void**)&h,   g_h);
    cudaGetSymbolAddress((void**)&q,   g_q);
    cudaGetSymbolAddress((void**)&k,   g_k);
    cudaGetSymbolAddress((void**)&v,   g_v);
    cudaGetSymbolAddress((void**)&att, g_att);
    cudaGetSymbolAddress((void**)&ff,  g_ff);

    // embedding
    {
        int n = MTOK * DMOD;
        embed_kernel<<<(n + 255) / 256, 256>>>(ids, emb, pe, x);
    }

    dim3 gD(DMOD / 64, MTOK / 64);   // N=768 GEMMs
    dim3 gF(FFD / 64, MTOK / 64);    // N=3072 GEMM

    for (int l = 0; l < LNUM; l++) {
        const float* lwq = wq + (size_t)l * DMOD * DMOD;
        const float* lwk = wk + (size_t)l * DMOD * DMOD;
        const float* lwv = wv + (size_t)l * DMOD * DMOD;
        const float* lwo = wo + (size_t)l * DMOD * DMOD;
        const float* lw1 = w1 + (size_t)l * DMOD * FFD;
        const float* lw2 = w2 + (size_t)l * FFD * DMOD;

        ln_kernel<<<MTOK, 256>>>(x, ln1w + l * DMOD, ln1b + l * DMOD, h);

        gemm_nn<0><<<gD, 256>>>(h, lwq, nullptr, nullptr, q, MTOK, DMOD, DMOD);
        gemm_nn<0><<<gD, 256>>>(h, lwk, nullptr, nullptr, k, MTOK, DMOD, DMOD);
        gemm_nn<0><<<gD, 256>>>(h, lwv, nullptr, nullptr, v, MTOK, DMOD, DMOD);

        attn_kernel<<<dim3(SEQ, HNUM, BAT), 128>>>(q, k, v, amask, att);

        // x = x + att @ wo
        gemm_nn<EP_RES><<<gD, 256>>>(att, lwo, nullptr, x, x, MTOK, DMOD, DMOD);

        ln_kernel<<<MTOK, 256>>>(x, ln2w + l * DMOD, ln2b + l * DMOD, h);

        // ff = gelu(h @ w1 + b1)
        gemm_nn<EP_BIAS | EP_GELU><<<gF, 256>>>(h, lw1, b1 + (size_t)l * FFD, nullptr, ff, MTOK, FFD, DMOD);
        // x = x + ff @ w2 + b2
        gemm_nn<EP_BIAS | EP_RES><<<gD, 256>>>(ff, lw2, b2 + (size_t)l * DMOD, x, x, MTOK, DMOD, FFD);
    }

    ln_kernel<<<MTOK, 256>>>(x, lnfw, lnfb, h);

    // logits = h @ emb^T
    dim3 gV((VOC + 63) / 64, MTOK / 64);
    gemm_nt<<<gV, 256>>>(h, emb, out, MTOK, VOC, DMOD);
}

// round 3
// speedup vs baseline: 1.2399x; 1.2399x over previous
#include <cuda_runtime.h>
#include <cuda_bf16.h>
#include <mma.h>
#include <math.h>
using namespace nvcuda;

#define LNUM 6
#define DMOD 768
#define HNUM 12
#define DKH  64
#define FFD  3072
#define VOC  50257
#define SEQ  1024
#define BAT  2
#define MTOK (BAT*SEQ)   // 2048
#define QKVN (3*DMOD)    // 2304

// ---------------- device scratch ----------------
__device__ float g_x   [MTOK*DMOD];
__device__ float g_h   [MTOK*DMOD];
__device__ float g_qkv [MTOK*QKVN];
__device__ float g_att [MTOK*DMOD];
__device__ float g_ff  [MTOK*FFD];

// ---------------- small kernels ----------------
__global__ void embed_kernel(const int* __restrict__ ids, const float* __restrict__ emb,
                             const float* __restrict__ pe, float* __restrict__ X) {
    int i = blockIdx.x * blockDim.x + threadIdx.x;
    if (i >= MTOK * DMOD) return;
    int d = i % DMOD, t = i / DMOD, s = t % SEQ;
    X[i] = emb[(size_t)ids[t] * DMOD + d] + pe[s * DMOD + d];
}

__global__ void ln_kernel(const float* __restrict__ X, const float* __restrict__ w,
                          const float* __restrict__ bvec, float* __restrict__ Y) {
    __shared__ float red[256];
    int row = blockIdx.x, tid = threadIdx.x;
    const float* x = X + (size_t)row * DMOD;
    float s = 0.f;
    for (int i = tid; i < DMOD; i += 256) s += x[i];
    red[tid] = s; __syncthreads();
    for (int o = 128; o > 0; o >>= 1) { if (tid < o) red[tid] += red[tid + o]; __syncthreads(); }
    float mu = red[0] * (1.0f / DMOD); __syncthreads();
    float v = 0.f;
    for (int i = tid; i < DMOD; i += 256) { float t = x[i] - mu; v += t * t; }
    red[tid] = v; __syncthreads();
    for (int o = 128; o > 0; o >>= 1) { if (tid < o) red[tid] += red[tid + o]; __syncthreads(); }
    float rstd = rsqrtf(red[0] * (1.0f / DMOD) + 1e-5f);
    float* y = Y + (size_t)row * DMOD;
    for (int i = tid; i < DMOD; i += 256) y[i] = (x[i] - mu) * rstd * w[i] + bvec[i];
}

// ---------------- WMMA bf16x3 GEMM ----------------
// C[M,N] = A[M,K] @ B ; A row-major. BCOL=false: B row-major [K,N] (ldb = row stride).
// BCOL=true: B col-major, i.e. B(k,n) = Bptr[n*ldb + k]  (lm_head: emb[V,D], ldb=D).
// Markidis split: A=Ah+Al, B=Bh+Bl (bf16); C += Ah*Bh + Ah*Bl + Al*Bh (fp32 accum).
#define EP_BIAS 1
#define EP_GELU 2
#define EP_RES  4

__device__ __forceinline__ float gelu_exact(float x) {
    return 0.5f * x * (1.0f + erff(x * 0.70710678118654752f));
}

// smem layout (halves): Ah[128*40], Al[128*40], Bh[128*40], Bl[128*40]  (B row-case uses [32][136] inside)
#define TA_LD 40
#define TB_LD_ROW 136
#define TILE_HALVES (128*40)
#define STAGE_LD 20
#define GEMM_SMEM (4*TILE_HALVES*2 + 8*16*STAGE_LD*4)

__device__ __forceinline__ void cvt_store4(__nv_bfloat16* hi, __nv_bfloat16* lo, float4 v) {
    __nv_bfloat16 h0 = __float2bfloat16(v.x), h1 = __float2bfloat16(v.y);
    __nv_bfloat16 h2 = __float2bfloat16(v.z), h3 = __float2bfloat16(v.w);
    __nv_bfloat16 l0 = __float2bfloat16(v.x - __bfloat162float(h0));
    __nv_bfloat16 l1 = __float2bfloat16(v.y - __bfloat162float(h1));
    __nv_bfloat16 l2 = __float2bfloat16(v.z - __bfloat162float(h2));
    __nv_bfloat16 l3 = __float2bfloat16(v.w - __bfloat162float(h3));
    *reinterpret_cast<__nv_bfloat162*>(hi)     = __nv_bfloat162(h0, h1);
    *reinterpret_cast<__nv_bfloat162*>(hi + 2) = __nv_bfloat162(h2, h3);
    *reinterpret_cast<__nv_bfloat162*>(lo)     = __nv_bfloat162(l0, l1);
    *reinterpret_cast<__nv_bfloat162*>(lo + 2) = __nv_bfloat162(l2, l3);
}

template<int EP, bool BCOL, bool NG>
__global__ void __launch_bounds__(256, 1)
gemm_tc(const float* __restrict__ A, const float* __restrict__ B,
        const float* __restrict__ bias, const float* __restrict__ res,
        float* __restrict__ C, int M, int N, int K, int ldb, int ldc) {
    extern __shared__ char smem[];
    __nv_bfloat16* Ah = reinterpret_cast<__nv_bfloat16*>(smem);
    __nv_bfloat16* Al = Ah + TILE_HALVES;
    __nv_bfloat16* Bh = Al + TILE_HALVES;
    __nv_bfloat16* Bl = Bh + TILE_HALVES;
    float* stage = reinterpret_cast<float*>(Bl + TILE_HALVES);

    int tid = threadIdx.x, lane = tid & 31, wid = tid >> 5;
    int warp_m = wid & 3, warp_n = wid >> 2;
    int bm = blockIdx.y * 128, bn = blockIdx.x * 128;

    wmma::fragment<wmma::accumulator, 16, 16, 16, float> acc[2][4];
    #pragma unroll
    for (int i = 0; i < 2; i++)
        #pragma unroll
        for (int j = 0; j < 4; j++) wmma::fill_fragment(acc[i][j], 0.f);

    int nch = K >> 5;
    float4 ra[4], rb[4];

    // ---- prefetch chunk 0 ----
    {
        int k0 = 0;
        #pragma unroll
        for (int i = 0; i < 4; i++) {
            int f4 = tid + i * 256;
            int r = f4 >> 3, c4 = f4 & 7;
            ra[i] = *reinterpret_cast<const float4*>(A + (size_t)(bm + r) * K + k0 + c4 * 4);
        }
        #pragma unroll
        for (int i = 0; i < 4; i++) {
            int f4 = tid + i * 256;
            if (BCOL) {
                int r = f4 >> 3, c4 = f4 & 7;
                int gn = bn + r;
                rb[i] = (NG && gn >= N) ? make_float4(0.f,0.f,0.f,0.f)
                        : *reinterpret_cast<const float4*>(B + (size_t)gn * ldb + k0 + c4 * 4);
            } else {
                int r = f4 >> 5, c4 = f4 & 31;
                rb[i] = *reinterpret_cast<const float4*>(B + (size_t)(k0 + r) * ldb + bn + c4 * 4);
            }
        }
    }

    for (int c = 0; c < nch; c++) {
        // ---- store + convert current chunk ----
        #pragma unroll
        for (int i = 0; i < 4; i++) {
            int f4 = tid + i * 256;
            int r = f4 >> 3, c4 = f4 & 7;
            int off = r * TA_LD + c4 * 4;
            cvt_store4(Ah + off, Al + off, ra[i]);
        }
        #pragma unroll
        for (int i = 0; i < 4; i++) {
            int f4 = tid + i * 256;
            int off;
            if (BCOL) { int r = f4 >> 3, c4 = f4 & 7;  off = r * TA_LD + c4 * 4; }
            else      { int r = f4 >> 5, c4 = f4 & 31; off = r * TB_LD_ROW + c4 * 4; }
            cvt_store4(Bh + off, Bl + off, rb[i]);
        }
        __syncthreads();

        // ---- prefetch next chunk ----
        if (c + 1 < nch) {
            int k0 = (c + 1) * 32;
            #pragma unroll
            for (int i = 0; i < 4; i++) {
                int f4 = tid + i * 256;
                int r = f4 >> 3, c4 = f4 & 7;
                ra[i] = *reinterpret_cast<const float4*>(A + (size_t)(bm + r) * K + k0 + c4 * 4);
            }
            #pragma unroll
            for (int i = 0; i < 4; i++) {
                int f4 = tid + i * 256;
                if (BCOL) {
                    int r = f4 >> 3, c4 = f4 & 7;
                    int gn = bn + r;
                    rb[i] = (NG && gn >= N) ? make_float4(0.f,0.f,0.f,0.f)
                            : *reinterpret_cast<const float4*>(B + (size_t)gn * ldb + k0 + c4 * 4);
                } else {
                    int r = f4 >> 5, c4 = f4 & 31;
                    rb[i] = *reinterpret_cast<const float4*>(B + (size_t)(k0 + r) * ldb + bn + c4 * 4);
                }
            }
        }

        // ---- MMA on this chunk (2 k16 steps) ----
        #pragma unroll
        for (int kk = 0; kk < 2; kk++) {
            wmma::fragment<wmma::matrix_a, 16, 16, 16, __nv_bfloat16, wmma::row_major> ah[2], al[2];
            #pragma unroll
            for (int i = 0; i < 2; i++) {
                const __nv_bfloat16* ap = Ah + (warp_m * 32 + i * 16) * TA_LD + kk * 16;
                const __nv_bfloat16* lp = Al + (warp_m * 32 + i * 16) * TA_LD + kk * 16;
                wmma::load_matrix_sync(ah[i], ap, TA_LD);
                wmma::load_matrix_sync(al[i], lp, TA_LD);
            }
            if (BCOL) {
                #pragma unroll
                for (int j = 0; j < 4; j++) {
                    wmma::fragment<wmma::matrix_b, 16, 16, 16, __nv_bfloat16, wmma::col_major> bh, bl;
                    const __nv_bfloat16* bp = Bh + (warp_n * 64 + j * 16) * TA_LD + kk * 16;
                    const __nv_bfloat16* lp = Bl + (warp_n * 64 + j * 16) * TA_LD + kk * 16;
                    wmma::load_matrix_sync(bh, bp, TA_LD);
                    wmma::load_matrix_sync(bl, lp, TA_LD);
                    #pragma unroll
                    for (int i = 0; i < 2; i++) {
                        wmma::mma_sync(acc[i][j], ah[i], bh, acc[i][j]);
                        wmma::mma_sync(acc[i][j], ah[i], bl, acc[i][j]);
                        wmma::mma_sync(acc[i][j], al[i], bh, acc[i][j]);
                    }
                }
            } else {
                #pragma unroll
                for (int j = 0; j < 4; j++) {
                    wmma::fragment<wmma::matrix_b, 16, 16, 16, __nv_bfloat16, wmma::row_major> bh, bl;
                    const __nv_bfloat16* bp = Bh + (kk * 16) * TB_LD_ROW + warp_n * 64 + j * 16;
                    const __nv_bfloat16* lp = Bl + (kk * 16) * TB_LD_ROW + warp_n * 64 + j * 16;
                    wmma::load_matrix_sync(bh, bp, TB_LD_ROW);
                    wmma::load_matrix_sync(bl, lp, TB_LD_ROW);
                    #pragma unroll
                    for (int i = 0; i < 2; i++) {
                        wmma::mma_sync(acc[i][j], ah[i], bh, acc[i][j]);
                        wmma::mma_sync(acc[i][j], ah[i], bl, acc[i][j]);
                        wmma::mma_sync(acc[i][j], al[i], bh, acc[i][j]);
                    }
                }
            }
        }
        __syncthreads();
    }

    // ---- epilogue via per-warp smem staging ----
    float* st = stage + wid * (16 * STAGE_LD);
    int r = lane >> 1, cb = (lane & 1) * 8;
    #pragma unroll
    for (int i = 0; i < 2; i++) {
        #pragma unroll
        for (int j = 0; j < 4; j++) {
            wmma::store_matrix_sync(st, acc[i][j], STAGE_LD, wmma::mem_row_major);
            __syncwarp();
            int m = bm + warp_m * 32 + i * 16 + r;
            int n0 = bn + warp_n * 64 + j * 16 + cb;
            #pragma unroll
            for (int q = 0; q < 8; q++) {
                int n = n0 + q;
                float v = st[r * STAGE_LD + cb + q];
                if (EP & EP_BIAS) v += bias[n];
                if (EP & EP_GELU) v = gelu_exact(v);
                if (EP & EP_RES)  v += res[(size_t)m * ldc + n];
                if (!NG || n < N) C[(size_t)m * ldc + n] = v;
            }
            __syncwarp();
        }
    }
}

// ---------------- attention (SIMT, fused strided qkv) ----------------
__global__ void __launch_bounds__(128)
attn_kernel(const float* __restrict__ QKV, const int* __restrict__ amask,
            float* __restrict__ O) {
    __shared__ float sc[SEQ];
    __shared__ float qrow[DKH];
    __shared__ float red[128];
    int b = blockIdx.z, h = blockIdx.y, qi = blockIdx.x;
    int tid = threadIdx.x;
    int len = qi + 1;
    const float scale = 0.125f;
    size_t base = (size_t)(b * SEQ + qi) * QKVN + h * DKH;

    if (tid < DKH) qrow[tid] = QKV[base + tid];
    __syncthreads();

    float lmax = -INFINITY;
    for (int kk = tid; kk < len; kk += 128) {
        const float4* kp = reinterpret_cast<const float4*>(QKV + (size_t)(b * SEQ + kk) * QKVN + DMOD + h * DKH);
        float dot = 0.f;
        #pragma unroll
        for (int i = 0; i < 16; i++) {
            float4 kv = kp[i];
            float4 qv = reinterpret_cast<const float4*>(qrow)[i];
            dot += kv.x*qv.x + kv.y*qv.y + kv.z*qv.z + kv.w*qv.w;
        }
        float s = dot * scale;
        if (amask[b * SEQ + kk] == 0) s = -1e9f;
        sc[kk] = s;
        lmax = fmaxf(lmax, s);
    }
    red[tid] = lmax; __syncthreads();
    for (int o = 64; o > 0; o >>= 1) { if (tid < o) red[tid] = fmaxf(red[tid], red[tid + o]); __syncthreads(); }
    float mx = red[0]; __syncthreads();

    float lsum = 0.f;
    for (int kk = tid; kk < len; kk += 128) {
        float e = expf(sc[kk] - mx);
        sc[kk] = e; lsum += e;
    }
    red[tid] = lsum; __syncthreads();
    for (int o = 64; o > 0; o >>= 1) { if (tid < o) red[tid] += red[tid + o]; __syncthreads(); }
    float inv = 1.0f / red[0]; __syncthreads();

    int d = tid & 63, half = tid >> 6;
    float acc = 0.f;
    for (int kk = half; kk < len; kk += 2)
        acc += sc[kk] * QKV[(size_t)(b * SEQ + kk) * QKVN + 2 * DMOD + h * DKH + d];
    red[tid] = acc; __syncthreads();
    if (half == 0)
        O[(size_t)(b * SEQ + qi) * DMOD + h * DKH + d] = (red[d] + red[d + 64]) * inv;
}

// ---------------- launch ----------------
extern "C" void kernel_launch(void* const* d_in, const int* in_sizes, int n_in,
                              void* d_out, int out_size) {
    const int*   ids   = (const int*)  d_in[0];
    const int*   amask = (const int*)  d_in[1];
    const float* emb   = (const float*)d_in[2];
    const float* pe    = (const float*)d_in[3];
    const float* wq    = (const float*)d_in[4];
    const float* wk    = (const float*)d_in[5];
    const float* wv    = (const float*)d_in[6];
    const float* wo    = (const float*)d_in[7];
    const float* ln1w  = (const float*)d_in[8];
    const float* ln1b  = (const float*)d_in[9];
    const float* ln2w  = (const float*)d_in[10];
    const float* ln2b  = (const float*)d_in[11];
    const float* w1    = (const float*)d_in[12];
    const float* b1    = (const float*)d_in[13];
    const float* w2    = (const float*)d_in[14];
    const float* b2    = (const float*)d_in[15];
    const float* lnfw  = (const float*)d_in[16];
    const float* lnfb  = (const float*)d_in[17];
    float* out = (float*)d_out;

    float *x, *h, *qkv, *att, *ff;
    cudaGetSymbolAddress((void**)&x,   g_x);
    cudaGetSymbolAddress((void**)&h,   g_h);
    cudaGetSymbolAddress((void**)&qkv, g_qkv);
    cudaGetSymbolAddress((void**)&att, g_att);
    cudaGetSymbolAddress((void**)&ff,  g_ff);

    cudaFuncSetAttribute(gemm_tc<0, false, false>,                 cudaFuncAttributeMaxDynamicSharedMemorySize, GEMM_SMEM);
    cudaFuncSetAttribute(gemm_tc<EP_RES, false, false>,            cudaFuncAttributeMaxDynamicSharedMemorySize, GEMM_SMEM);
    cudaFuncSetAttribute(gemm_tc<EP_BIAS | EP_GELU, false, false>, cudaFuncAttributeMaxDynamicSharedMemorySize, GEMM_SMEM);
    cudaFuncSetAttribute(gemm_tc<EP_BIAS | EP_RES, false, false>,  cudaFuncAttributeMaxDynamicSharedMemorySize, GEMM_SMEM);
    cudaFuncSetAttribute(gemm_tc<0, true, true>,                   cudaFuncAttributeMaxDynamicSharedMemorySize, GEMM_SMEM);

    { int n = MTOK * DMOD; embed_kernel<<<(n + 255) / 256, 256>>>(ids, emb, pe, x); }

    dim3 gD(DMOD / 128, MTOK / 128);   // 6 x 16
    dim3 gF(FFD / 128, MTOK / 128);    // 24 x 16

    for (int l = 0; l < LNUM; l++) {
        const float* lwq = wq + (size_t)l * DMOD * DMOD;
        const float* lwk = wk + (size_t)l * DMOD * DMOD;
        const float* lwv = wv + (size_t)l * DMOD * DMOD;
        const float* lwo = wo + (size_t)l * DMOD * DMOD;
        const float* lw1 = w1 + (size_t)l * DMOD * FFD;
        const float* lw2 = w2 + (size_t)l * FFD * DMOD;

        ln_kernel<<<MTOK, 256>>>(x, ln1w + l * DMOD, ln1b + l * DMOD, h);

        gemm_tc<0, false, false><<<gD, 256, GEMM_SMEM>>>(h, lwq, nullptr, nullptr, qkv + 0,        MTOK, DMOD, DMOD, DMOD, QKVN);
        gemm_tc<0, false, false><<<gD, 256, GEMM_SMEM>>>(h, lwk, nullptr, nullptr, qkv + DMOD,     MTOK, DMOD, DMOD, DMOD, QKVN);
        gemm_tc<0, false, false><<<gD, 256, GEMM_SMEM>>>(h, lwv, nullptr, nullptr, qkv + 2 * DMOD, MTOK, DMOD, DMOD, DMOD, QKVN);

        attn_kernel<<<dim3(SEQ, HNUM, BAT), 128>>>(qkv, amask, att);

        gemm_tc<EP_RES, false, false><<<gD, 256, GEMM_SMEM>>>(att, lwo, nullptr, x, x, MTOK, DMOD, DMOD, DMOD, DMOD);

        ln_kernel<<<MTOK, 256>>>(x, ln2w + l * DMOD, ln2b + l * DMOD, h);

        gemm_tc<EP_BIAS | EP_GELU, false, false><<<gF, 256, GEMM_SMEM>>>(h, lw1, b1 + (size_t)l * FFD, nullptr, ff, MTOK, FFD, DMOD, FFD, FFD);
        gemm_tc<EP_BIAS | EP_RES, false, false><<<gD, 256, GEMM_SMEM>>>(ff, lw2, b2 + (size_t)l * DMOD, x, x, MTOK, DMOD, FFD, DMOD, DMOD);
    }

    ln_kernel<<<MTOK, 256>>>(x, lnfw, lnfb, h);

    dim3 gV((VOC + 127) / 128, MTOK / 128);
    gemm_tc<0, true, true><<<gV, 256, GEMM_SMEM>>>(h, emb, nullptr, nullptr, out, MTOK, VOC, DMOD, DMOD, VOC);
}

// round 5
// speedup vs baseline: 2.0681x; 1.6679x over previous
#include <cuda_runtime.h>
#include <cuda_bf16.h>
#include <mma.h>
#include <math.h>
#include <cstdint>
#include <cstddef>
using namespace nvcuda;

#define LNUM 6
#define DMOD 768
#define HNUM 12
#define DKH  64
#define FFD  3072
#define VOC  50257
#define SEQ  1024
#define BAT  2
#define MTOK (BAT*SEQ)   // 2048
#define QKVN (3*DMOD)    // 2304

// ---------------- device scratch ----------------
__device__ float g_x  [MTOK*DMOD];
__device__ float g_qkv[MTOK*QKVN];
__device__ __nv_bfloat16 g_h_h [MTOK*DMOD],  g_h_l [MTOK*DMOD];
__device__ __nv_bfloat16 g_att_h[MTOK*DMOD], g_att_l[MTOK*DMOD];
__device__ __nv_bfloat16 g_ff_h[MTOK*FFD],   g_ff_l[MTOK*FFD];
// pre-split weights
__device__ __nv_bfloat16 g_wqkv_h[LNUM*DMOD*QKVN], g_wqkv_l[LNUM*DMOD*QKVN];
__device__ __nv_bfloat16 g_wo_h [LNUM*DMOD*DMOD],  g_wo_l [LNUM*DMOD*DMOD];
__device__ __nv_bfloat16 g_w1_h [LNUM*DMOD*FFD],   g_w1_l [LNUM*DMOD*FFD];
__device__ __nv_bfloat16 g_w2_h [LNUM*FFD*DMOD],   g_w2_l [LNUM*FFD*DMOD];
__device__ __nv_bfloat16 g_emb_h[VOC*DMOD],        g_emb_l[VOC*DMOD];

// ---------------- helpers ----------------
__device__ __forceinline__ uint32_t smem_u32(const void* p) {
    uint32_t a;
    asm("{ .reg .u64 t; cvta.to.shared.u64 t, %1; cvt.u32.u64 %0, t; }" : "=r"(a) : "l"(p));
    return a;
}
__device__ __forceinline__ void cpa16(uint32_t dst, const void* src) {
    asm volatile("cp.async.cg.shared.global [%0], [%1], 16;" :: "r"(dst), "l"(src));
}
#define CP_COMMIT() asm volatile("cp.async.commit_group;" ::: "memory")
#define CP_WAIT1()  asm volatile("cp.async.wait_group 1;" ::: "memory")

__device__ __forceinline__ void split2(float v, __nv_bfloat16& hi, __nv_bfloat16& lo) {
    hi = __float2bfloat16(v);
    lo = __float2bfloat16(v - __bfloat162float(hi));
}

// ---------------- prepass split kernels ----------------
__global__ void split_kernel(const float* __restrict__ src, __nv_bfloat16* __restrict__ hi,
                             __nv_bfloat16* __restrict__ lo, int n) {
    int i = blockIdx.x * blockDim.x + threadIdx.x;
    if (i >= n) return;
    split2(src[i], hi[i], lo[i]);
}
__global__ void build_qkv_kernel(const float* __restrict__ wq, const float* __restrict__ wk,
                                 const float* __restrict__ wv,
                                 __nv_bfloat16* __restrict__ hi, __nv_bfloat16* __restrict__ lo) {
    int i = blockIdx.x * blockDim.x + threadIdx.x;
    if (i >= LNUM * DMOD * QKVN) return;
    int l = i / (DMOD * QKVN);
    int rem = i % (DMOD * QKVN);
    int k = rem / QKVN, j = rem % QKVN;
    const float* s = (j < DMOD) ? wq : (j < 2 * DMOD) ? wk : wv;
    float v = s[(size_t)l * DMOD * DMOD + (size_t)k * DMOD + (j % DMOD)];
    split2(v, hi[i], lo[i]);
}

// ---------------- embedding ----------------
__global__ void embed_kernel(const int* __restrict__ ids, const float* __restrict__ emb,
                             const float* __restrict__ pe, float* __restrict__ X) {
    int i = blockIdx.x * blockDim.x + threadIdx.x;
    if (i >= MTOK * DMOD) return;
    int d = i % DMOD, t = i / DMOD, s = t % SEQ;
    X[i] = emb[(size_t)ids[t] * DMOD + d] + pe[s * DMOD + d];
}

// ---------------- layernorm -> bf16 hi/lo ----------------
__global__ void ln_kernel(const float* __restrict__ X, const float* __restrict__ w,
                          const float* __restrict__ bvec,
                          __nv_bfloat16* __restrict__ Yh, __nv_bfloat16* __restrict__ Yl) {
    __shared__ float red[256];
    int row = blockIdx.x, tid = threadIdx.x;
    const float* x = X + (size_t)row * DMOD;
    float s = 0.f;
    for (int i = tid; i < DMOD; i += 256) s += x[i];
    red[tid] = s; __syncthreads();
    for (int o = 128; o > 0; o >>= 1) { if (tid < o) red[tid] += red[tid + o]; __syncthreads(); }
    float mu = red[0] * (1.0f / DMOD); __syncthreads();
    float v = 0.f;
    for (int i = tid; i < DMOD; i += 256) { float t = x[i] - mu; v += t * t; }
    red[tid] = v; __syncthreads();
    for (int o = 128; o > 0; o >>= 1) { if (tid < o) red[tid] += red[tid + o]; __syncthreads(); }
    float rstd = rsqrtf(red[0] * (1.0f / DMOD) + 1e-5f);
    for (int i = tid; i < DMOD; i += 256) {
        float y = (x[i] - mu) * rstd * w[i] + bvec[i];
        __nv_bfloat16 hi, lo; split2(y, hi, lo);
        Yh[(size_t)row * DMOD + i] = hi;
        Yl[(size_t)row * DMOD + i] = lo;
    }
}

// ---------------- GEMM: pre-split bf16, cp.async 3-stage, WMMA 3-term ----------------
#define EP_BIAS 1
#define EP_GELU 2
#define EP_RES  4

__device__ __forceinline__ float gelu_exact(float x) {
    return 0.5f * x * (1.0f + erff(x * 0.70710678118654752f));
}

template<int EP, bool BCOL, bool NG, int TN, bool WH>
__global__ void __launch_bounds__(256, 1)
gemm_tc(const __nv_bfloat16* __restrict__ Ah_g, const __nv_bfloat16* __restrict__ Al_g,
        const __nv_bfloat16* __restrict__ Bh_g, const __nv_bfloat16* __restrict__ Bl_g,
        const float* __restrict__ bias, const float* __restrict__ res,
        float* __restrict__ C, __nv_bfloat16* __restrict__ Chi, __nv_bfloat16* __restrict__ Clo,
        int M, int N, int K, int ldb, int ldc) {
    constexpr int ALD = 40;
    constexpr int BLD = BCOL ? 40 : (TN + 8);
    constexpr int ABYTES = 128 * ALD * 2;
    constexpr int BBYTES = BCOL ? (128 * 40 * 2) : (32 * BLD * 2);
    constexpr int STAGEB = 2 * (ABYTES + BBYTES);
    constexpr int NJ = TN / 32;      // j-subtiles per warp

    extern __shared__ char smem[];
    uint32_t sbase = smem_u32(smem);

    int tid = threadIdx.x, lane = tid & 31, wid = tid >> 5;
    int warp_m = wid & 3, warp_n = wid >> 2;
    int bm = blockIdx.y * 128, bn = blockIdx.x * TN;
    int nch = K >> 5;

    wmma::fragment<wmma::accumulator, 16, 16, 16, float> acc[2][NJ];
    #pragma unroll
    for (int i = 0; i < 2; i++)
        #pragma unroll
        for (int j = 0; j < NJ; j++) wmma::fill_fragment(acc[i][j], 0.f);

    auto load_stage = [&](int s, int c) {
        int k0 = c * 32;
        uint32_t abase = sbase + s * STAGEB;
        #pragma unroll
        for (int hn = 0; hn < 2; hn++) {
            const __nv_bfloat16* g = hn ? Al_g : Ah_g;
            uint32_t db = abase + hn * ABYTES;
            #pragma unroll
            for (int i = 0; i < 2; i++) {
                int cid = tid + i * 256;
                int r = cid >> 2, seg = cid & 3;
                cpa16(db + (uint32_t)(r * ALD + seg * 8) * 2,
                      g + (size_t)(bm + r) * K + k0 + seg * 8);
            }
        }
        uint32_t bbase = abase + 2 * ABYTES;
        if (BCOL) {
            #pragma unroll
            for (int hn = 0; hn < 2; hn++) {
                const __nv_bfloat16* g = hn ? Bl_g : Bh_g;
                uint32_t db = bbase + hn * BBYTES;
                #pragma unroll
                for (int i = 0; i < 2; i++) {
                    int cid = tid + i * 256;
                    int r = cid >> 2, seg = cid & 3;
                    int gn = bn + r;
                    uint32_t d = db + (uint32_t)(r * 40 + seg * 8) * 2;
                    if (!NG || gn < N)
                        cpa16(d, g + (size_t)gn * ldb + k0 + seg * 8);
                    else
                        *reinterpret_cast<uint4*>(smem + (d - sbase)) = make_uint4(0, 0, 0, 0);
                }
            }
        } else {
            constexpr int CH = TN / 8;
            constexpr int NIT = (32 * CH) / 256;
            #pragma unroll
            for (int hn = 0; hn < 2; hn++) {
                const __nv_bfloat16* g = hn ? Bl_g : Bh_g;
                uint32_t db = bbase + hn * BBYTES;
                #pragma unroll
                for (int i = 0; i < NIT; i++) {
                    int cid = tid + i * 256;
                    int kr = cid / CH, seg = cid % CH;
                    cpa16(db + (uint32_t)(kr * BLD + seg * 8) * 2,
                          g + (size_t)(k0 + kr) * ldb + bn + seg * 8);
                }
            }
        }
        CP_COMMIT();
    };

    auto do_mma = [&](int s) {
        char* base = smem + s * STAGEB;
        __nv_bfloat16* Ah = reinterpret_cast<__nv_bfloat16*>(base);
        __nv_bfloat16* Al = reinterpret_cast<__nv_bfloat16*>(base + ABYTES);
        __nv_bfloat16* Bh = reinterpret_cast<__nv_bfloat16*>(base + 2 * ABYTES);
        __nv_bfloat16* Bl = reinterpret_cast<__nv_bfloat16*>(base + 2 * ABYTES + BBYTES);
        #pragma unroll
        for (int kk = 0; kk < 2; kk++) {
            wmma::fragment<wmma::matrix_a, 16, 16, 16, __nv_bfloat16, wmma::row_major> ah[2], al[2];
            #pragma unroll
            for (int i = 0; i < 2; i++) {
                wmma::load_matrix_sync(ah[i], Ah + (warp_m * 32 + i * 16) * ALD + kk * 16, ALD);
                wmma::load_matrix_sync(al[i], Al + (warp_m * 32 + i * 16) * ALD + kk * 16, ALD);
            }
            #pragma unroll
            for (int j = 0; j < NJ; j++) {
                if (BCOL) {
                    wmma::fragment<wmma::matrix_b, 16, 16, 16, __nv_bfloat16, wmma::col_major> bh, bl;
                    wmma::load_matrix_sync(bh, Bh + (warp_n * (TN / 2) + j * 16) * 40 + kk * 16, 40);
                    wmma::load_matrix_sync(bl, Bl + (warp_n * (TN / 2) + j * 16) * 40 + kk * 16, 40);
                    #pragma unroll
                    for (int i = 0; i < 2; i++) {
                        wmma::mma_sync(acc[i][j], ah[i], bh, acc[i][j]);
                        wmma::mma_sync(acc[i][j], ah[i], bl, acc[i][j]);
                        wmma::mma_sync(acc[i][j], al[i], bh, acc[i][j]);
                    }
                } else {
                    wmma::fragment<wmma::matrix_b, 16, 16, 16, __nv_bfloat16, wmma::row_major> bh, bl;
                    wmma::load_matrix_sync(bh, Bh + (kk * 16) * BLD + warp_n * (TN / 2) + j * 16, BLD);
                    wmma::load_matrix_sync(bl, Bl + (kk * 16) * BLD + warp_n * (TN / 2) + j * 16, BLD);
                    #pragma unroll
                    for (int i = 0; i < 2; i++) {
                        wmma::mma_sync(acc[i][j], ah[i], bh, acc[i][j]);
                        wmma::mma_sync(acc[i][j], ah[i], bl, acc[i][j]);
                        wmma::mma_sync(acc[i][j], al[i], bh, acc[i][j]);
                    }
                }
            }
        }
    };

    // prologue: chunks 0,1
    load_stage(0, 0);
    load_stage(1, 1);
    for (int c = 0; c < nch; c++) {
        CP_WAIT1();
        __syncthreads();
        if (c + 2 < nch) load_stage((c + 2) % 3, c + 2);
        do_mma(c % 3);
    }
    __syncthreads();

    // epilogue: per-warp smem staging (reuse stage 0)
    float* stg = reinterpret_cast<float*>(smem) + wid * (16 * 20);
    int r = lane >> 1, cb = (lane & 1) * 8;
    #pragma unroll
    for (int i = 0; i < 2; i++) {
        #pragma unroll
        for (int j = 0; j < NJ; j++) {
            wmma::store_matrix_sync(stg, acc[i][j], 20, wmma::mem_row_major);
            __syncwarp();
            int m = bm + warp_m * 32 + i * 16 + r;
            int n0 = bn + warp_n * (TN / 2) + j * 16 + cb;
            #pragma unroll
            for (int q = 0; q < 8; q++) {
                int n = n0 + q;
                float v = stg[r * 20 + cb + q];
                if (EP & EP_BIAS) v += bias[n];
                if (EP & EP_GELU) v = gelu_exact(v);
                if (EP & EP_RES)  v += res[(size_t)m * ldc + n];
                if (!NG || n < N) {
                    if (WH) {
                        __nv_bfloat16 hi, lo; split2(v, hi, lo);
                        Chi[(size_t)m * ldc + n] = hi;
                        Clo[(size_t)m * ldc + n] = lo;
                    } else {
                        C[(size_t)m * ldc + n] = v;
                    }
                }
            }
            __syncwarp();
        }
    }
}

// ---------------- flash-style SIMT attention ----------------
// block: 64 q-rows of one (b,h); 64-key tiles; online softmax; fp32 internal.
#define APD 68
#define ATT_SMEM ((4*64*APD + 3*64)*4 + 64*4)

__global__ void __launch_bounds__(256)
attn_kernel(const float* __restrict__ QKV, const int* __restrict__ amask,
            __nv_bfloat16* __restrict__ Oh, __nv_bfloat16* __restrict__ Ol) {
    extern __shared__ char asmem[];
    float* Qt = reinterpret_cast<float*>(asmem);            // [d][i]
    float* Kt = Qt + 64 * APD;                              // [d][j]
    float* Vs = Kt + 64 * APD;                              // [j][d]
    float* Pt = Vs + 64 * APD;                              // [j][i]
    float* sm_m = Pt + 64 * APD;
    float* sm_l = sm_m + 64;
    float* sm_s = sm_l + 64;
    int*   msk  = reinterpret_cast<int*>(sm_s + 64);

    int b = blockIdx.z, h = blockIdx.y, qt = blockIdx.x;
    int tid = threadIdx.x;
    int q0 = qt * 64;
    int ty = tid >> 4, tx = tid & 15;

    for (int idx = tid; idx < 64 * 64; idx += 256) {
        int i = idx >> 6, d = idx & 63;
        Qt[d * APD + i] = QKV[(size_t)(b * SEQ + q0 + i) * QKVN + h * DKH + d] * 0.125f;
    }
    if (tid < 64) { sm_m[tid] = -1e30f; sm_l[tid] = 0.f; }

    float o[4][4] = {};
    int ntile = qt + 1;

    for (int kt = 0; kt < ntile; kt++) {
        int k0 = kt * 64;
        __syncthreads();
        for (int idx = tid; idx < 64 * 64; idx += 256) {
            int j = idx >> 6, d = idx & 63;
            Kt[d * APD + j] = QKV[(size_t)(b * SEQ + k0 + j) * QKVN + DMOD + h * DKH + d];
        }
        for (int idx = tid; idx < 64 * 16; idx += 256) {
            int j = idx >> 4, s4 = idx & 15;
            float4 vv = *reinterpret_cast<const float4*>(
                &QKV[(size_t)(b * SEQ + k0 + j) * QKVN + 2 * DMOD + h * DKH + s4 * 4]);
            *reinterpret_cast<float4*>(&Vs[j * APD + s4 * 4]) = vv;
        }
        if (tid < 64) msk[tid] = amask[b * SEQ + k0 + tid];
        __syncthreads();

        // scores
        float s[4][4] = {};
        for (int d = 0; d < 64; d++) {
            float4 qv = *reinterpret_cast<float4*>(&Qt[d * APD + ty * 4]);
            float4 kv = *reinterpret_cast<float4*>(&Kt[d * APD + tx * 4]);
            float qa[4] = {qv.x, qv.y, qv.z, qv.w};
            float ka[4] = {kv.x, kv.y, kv.z, kv.w};
            #pragma unroll
            for (int rr = 0; rr < 4; rr++)
                #pragma unroll
                for (int cc = 0; cc < 4; cc++) s[rr][cc] += qa[rr] * ka[cc];
        }
        #pragma unroll
        for (int rr = 0; rr < 4; rr++)
            #pragma unroll
            for (int cc = 0; cc < 4; cc++) {
                int i = ty * 4 + rr, j = tx * 4 + cc;
                float v = s[rr][cc];
                if (msk[j] == 0 || (k0 + j) > (q0 + i)) v = -1e9f;
                Pt[j * APD + i] = v;
            }
        __syncthreads();

        // online softmax update
        {
            int row = tid >> 2, qq = tid & 3;
            float tmax = -1e30f;
            #pragma unroll
            for (int jj = 0; jj < 16; jj++) tmax = fmaxf(tmax, Pt[(qq * 16 + jj) * APD + row]);
            tmax = fmaxf(tmax, __shfl_xor_sync(0xffffffff, tmax, 1));
            tmax = fmaxf(tmax, __shfl_xor_sync(0xffffffff, tmax, 2));
            float mold = sm_m[row];
            float newm = fmaxf(mold, tmax);
            float psum = 0.f;
            #pragma unroll
            for (int jj = 0; jj < 16; jj++) {
                int j = qq * 16 + jj;
                float p = __expf(Pt[j * APD + row] - newm);
                Pt[j * APD + row] = p;
                psum += p;
            }
            psum += __shfl_xor_sync(0xffffffff, psum, 1);
            psum += __shfl_xor_sync(0xffffffff, psum, 2);
            if (qq == 0) {
                float sc = __expf(mold - newm);
                sm_s[row] = sc;
                sm_l[row] = sm_l[row] * sc + psum;
                sm_m[row] = newm;
            }
        }
        __syncthreads();

        // rescale + PV
        {
            float sc[4];
            #pragma unroll
            for (int rr = 0; rr < 4; rr++) sc[rr] = sm_s[ty * 4 + rr];
            #pragma unroll
            for (int rr = 0; rr < 4; rr++)
                #pragma unroll
                for (int cc = 0; cc < 4; cc++) o[rr][cc] *= sc[rr];
            for (int j = 0; j < 64; j++) {
                float4 pv = *reinterpret_cast<float4*>(&Pt[j * APD + ty * 4]);
                float4 vv = *reinterpret_cast<float4*>(&Vs[j * APD + tx * 4]);
                float pa[4] = {pv.x, pv.y, pv.z, pv.w};
                float va[4] = {vv.x, vv.y, vv.z, vv.w};
                #pragma unroll
                for (int rr = 0; rr < 4; rr++)
                    #pragma unroll
                    for (int cc = 0; cc < 4; cc++) o[rr][cc] += pa[rr] * va[cc];
            }
        }
    }
    __syncthreads();
    {
        float inv[4];
        #pragma unroll
        for (int rr = 0; rr < 4; rr++) inv[rr] = 1.0f / sm_l[ty * 4 + rr];
        #pragma unroll
        for (int rr = 0; rr < 4; rr++)
            #pragma unroll
            for (int cc = 0; cc < 4; cc++) {
                size_t off = (size_t)(b * SEQ + q0 + ty * 4 + rr) * DMOD + h * DKH + tx * 4 + cc;
                float v = o[rr][cc] * inv[rr];
                __nv_bfloat16 hi, lo; split2(v, hi, lo);
                Oh[off] = hi; Ol[off] = lo;
            }
    }
}

// ---------------- launch ----------------
extern "C" void kernel_launch(void* const* d_in, const int* in_sizes, int n_in,
                              void* d_out, int out_size) {
    const int*   ids   = (const int*)  d_in[0];
    const int*   amask = (const int*)  d_in[1];
    const float* emb   = (const float*)d_in[2];
    const float* pe    = (const float*)d_in[3];
    const float* wq    = (const float*)d_in[4];
    const float* wk    = (const float*)d_in[5];
    const float* wv    = (const float*)d_in[6];
    const float* wo    = (const float*)d_in[7];
    const float* ln1w  = (const float*)d_in[8];
    const float* ln1b  = (const float*)d_in[9];
    const float* ln2w  = (const float*)d_in[10];
    const float* ln2b  = (const float*)d_in[11];
    const float* w1    = (const float*)d_in[12];
    const float* b1    = (const float*)d_in[13];
    const float* w2    = (const float*)d_in[14];
    const float* b2    = (const float*)d_in[15];
    const float* lnfw  = (const float*)d_in[16];
    const float* lnfb  = (const float*)d_in[17];
    float* out = (float*)d_out;

    float *x, *qkv;
    __nv_bfloat16 *h_h, *h_l, *att_h, *att_l, *ff_h, *ff_l;
    __nv_bfloat16 *wqkv_h, *wqkv_l, *wo_h, *wo_l, *w1_h, *w1_l, *w2_h, *w2_l, *emb_h, *emb_l;
    cudaGetSymbolAddress((void**)&x,     g_x);
    cudaGetSymbolAddress((void**)&qkv,   g_qkv);
    cudaGetSymbolAddress((void**)&h_h,   g_h_h);   cudaGetSymbolAddress((void**)&h_l,   g_h_l);
    cudaGetSymbolAddress((void**)&att_h, g_att_h); cudaGetSymbolAddress((void**)&att_l, g_att_l);
    cudaGetSymbolAddress((void**)&ff_h,  g_ff_h);  cudaGetSymbolAddress((void**)&ff_l,  g_ff_l);
    cudaGetSymbolAddress((void**)&wqkv_h, g_wqkv_h); cudaGetSymbolAddress((void**)&wqkv_l, g_wqkv_l);
    cudaGetSymbolAddress((void**)&wo_h,  g_wo_h);  cudaGetSymbolAddress((void**)&wo_l,  g_wo_l);
    cudaGetSymbolAddress((void**)&w1_h,  g_w1_h);  cudaGetSymbolAddress((void**)&w1_l,  g_w1_l);
    cudaGetSymbolAddress((void**)&w2_h,  g_w2_h);  cudaGetSymbolAddress((void**)&w2_l,  g_w2_l);
    cudaGetSymbolAddress((void**)&emb_h, g_emb_h); cudaGetSymbolAddress((void**)&emb_l, g_emb_l);

    // smem sizes per GEMM variant
    const int SM_T128 = 3 * (2 * (128 * 40 * 2) + 2 * (32 * 136 * 2));   // row-major B, TN=128
    const int SM_T64  = 3 * (2 * (128 * 40 * 2) + 2 * (32 * 72 * 2));    // row-major B, TN=64
    const int SM_COL  = 3 * (2 * (128 * 40 * 2) + 2 * (128 * 40 * 2));   // col-major B, TN=128

    cudaFuncSetAttribute(gemm_tc<0, false, false, 128, false>,                cudaFuncAttributeMaxDynamicSharedMemorySize, SM_T128);
    cudaFuncSetAttribute(gemm_tc<EP_RES, false, false, 64, false>,            cudaFuncAttributeMaxDynamicSharedMemorySize, SM_T64);
    cudaFuncSetAttribute(gemm_tc<EP_BIAS | EP_GELU, false, false, 128, true>, cudaFuncAttributeMaxDynamicSharedMemorySize, SM_T128);
    cudaFuncSetAttribute(gemm_tc<EP_BIAS | EP_RES, false, false, 64, false>,  cudaFuncAttributeMaxDynamicSharedMemorySize, SM_T64);
    cudaFuncSetAttribute(gemm_tc<0, true, true, 128, false>,                  cudaFuncAttributeMaxDynamicSharedMemorySize, SM_COL);
    cudaFuncSetAttribute(attn_kernel, cudaFuncAttributeMaxDynamicSharedMemorySize, ATT_SMEM);

    // ---- prepass: split weights/emb into bf16 hi/lo ----
    {
        int n;
        n = LNUM * DMOD * QKVN;
        build_qkv_kernel<<<(n + 255) / 256, 256>>>(wq, wk, wv, wqkv_h, wqkv_l);
        n = LNUM * DMOD * DMOD;
        split_kernel<<<(n + 255) / 256, 256>>>(wo, wo_h, wo_l, n);
        n = LNUM * DMOD * FFD;
        split_kernel<<<(n + 255) / 256, 256>>>(w1, w1_h, w1_l, n);
        n = LNUM * FFD * DMOD;
        split_kernel<<<(n + 255) / 256, 256>>>(w2, w2_h, w2_l, n);
        n = VOC * DMOD;
        split_kernel<<<(n + 255) / 256, 256>>>(emb, emb_h, emb_l, n);
    }

    { int n = MTOK * DMOD; embed_kernel<<<(n + 255) / 256, 256>>>(ids, emb, pe, x); }

    dim3 gQKV(QKVN / 128, MTOK / 128);   // 18 x 16
    dim3 gD64(DMOD / 64, MTOK / 128);    // 12 x 16
    dim3 gF(FFD / 128, MTOK / 128);      // 24 x 16

    for (int l = 0; l < LNUM; l++) {
        ln_kernel<<<MTOK, 256>>>(x, ln1w + l * DMOD, ln1b + l * DMOD, h_h, h_l);

        gemm_tc<0, false, false, 128, false><<<gQKV, 256, SM_T128>>>(
            h_h, h_l, wqkv_h + (size_t)l * DMOD * QKVN, wqkv_l + (size_t)l * DMOD * QKVN,
            nullptr, nullptr, qkv, nullptr, nullptr, MTOK, QKVN, DMOD, QKVN, QKVN);

        attn_kernel<<<dim3(SEQ / 64, HNUM, BAT), 256, ATT_SMEM>>>(qkv, amask, att_h, att_l);

        gemm_tc<EP_RES, false, false, 64, false><<<gD64, 256, SM_T64>>>(
            att_h, att_l, wo_h + (size_t)l * DMOD * DMOD, wo_l + (size_t)l * DMOD * DMOD,
            nullptr, x, x, nullptr, nullptr, MTOK, DMOD, DMOD, DMOD, DMOD);

        ln_kernel<<<MTOK, 256>>>(x, ln2w + l * DMOD, ln2b + l * DMOD, h_h, h_l);

        gemm_tc<EP_BIAS | EP_GELU, false, false, 128, true><<<gF, 256, SM_T128>>>(
            h_h, h_l, w1_h + (size_t)l * DMOD * FFD, w1_l + (size_t)l * DMOD * FFD,
            b1 + (size_t)l * FFD, nullptr, nullptr, ff_h, ff_l, MTOK, FFD, DMOD, FFD, FFD);

        gemm_tc<EP_BIAS | EP_RES, false, false, 64, false><<<gD64, 256, SM_T64>>>(
            ff_h, ff_l, w2_h + (size_t)l * FFD * DMOD, w2_l + (size_t)l * FFD * DMOD,
            b2 + (size_t)l * DMOD, x, x, nullptr, nullptr, MTOK, DMOD, FFD, DMOD, DMOD);
    }

    ln_kernel<<<MTOK, 256>>>(x, lnfw, lnfb, h_h, h_l);

    dim3 gV((VOC + 127) / 128, MTOK / 128);
    gemm_tc<0, true, true, 128, false><<<gV, 256, SM_COL>>>(
        h_h, h_l, emb_h, emb_l, nullptr, nullptr, out, nullptr, nullptr, MTOK, VOC, DMOD, DMOD, VOC);
}

// round 6
// speedup vs baseline: 2.3427x; 1.1328x over previous
#include <cuda_runtime.h>
#include <cuda_bf16.h>
#include <mma.h>
#include <math.h>
#include <cstdint>
#include <cstddef>
using namespace nvcuda;

#define LNUM 6
#define DMOD 768
#define HNUM 12
#define DKH  64
#define FFD  3072
#define VOC  50257
#define SEQ  1024
#define BAT  2
#define MTOK (BAT*SEQ)   // 2048
#define QKVN (3*DMOD)    // 2304

// ---------------- device scratch ----------------
__device__ float g_x  [MTOK*DMOD];
__device__ float g_qkv[MTOK*QKVN];
__device__ __nv_bfloat16 g_h_h [MTOK*DMOD],  g_h_l [MTOK*DMOD];
__device__ __nv_bfloat16 g_att_h[MTOK*DMOD], g_att_l[MTOK*DMOD];
__device__ __nv_bfloat16 g_ff_h[MTOK*FFD],   g_ff_l[MTOK*FFD];
// pre-split weights
__device__ __nv_bfloat16 g_wqkv_h[LNUM*DMOD*QKVN], g_wqkv_l[LNUM*DMOD*QKVN];
__device__ __nv_bfloat16 g_wo_h [LNUM*DMOD*DMOD],  g_wo_l [LNUM*DMOD*DMOD];
__device__ __nv_bfloat16 g_w1_h [LNUM*DMOD*FFD],   g_w1_l [LNUM*DMOD*FFD];
__device__ __nv_bfloat16 g_w2_h [LNUM*FFD*DMOD],   g_w2_l [LNUM*FFD*DMOD];
__device__ __nv_bfloat16 g_emb_h[VOC*DMOD],        g_emb_l[VOC*DMOD];

// ---------------- helpers ----------------
__device__ __forceinline__ uint32_t smem_u32(const void* p) {
    uint32_t a;
    asm("{ .reg .u64 t; cvta.to.shared.u64 t, %1; cvt.u32.u64 %0, t; }" : "=r"(a) : "l"(p));
    return a;
}
__device__ __forceinline__ void cpa16(uint32_t dst, const void* src) {
    asm volatile("cp.async.cg.shared.global [%0], [%1], 16;" :: "r"(dst), "l"(src));
}
#define CP_COMMIT() asm volatile("cp.async.commit_group;" ::: "memory")
#define CP_WAIT1()  asm volatile("cp.async.wait_group 1;" ::: "memory")

__device__ __forceinline__ void split2(float v, __nv_bfloat16& hi, __nv_bfloat16& lo) {
    hi = __float2bfloat16(v);
    lo = __float2bfloat16(v - __bfloat162float(hi));
}

// ---------------- merged prepass split kernel ----------------
#define N_QKV (LNUM*DMOD*QKVN)
#define N_WO  (LNUM*DMOD*DMOD)
#define N_W1  (LNUM*DMOD*FFD)
#define N_W2  (LNUM*FFD*DMOD)
#define N_EMB (VOC*DMOD)
#define N_SPLIT_TOT (N_QKV + N_WO + N_W1 + N_W2 + N_EMB)

__global__ void split_all_kernel(const float* __restrict__ wq, const float* __restrict__ wk,
                                 const float* __restrict__ wv, const float* __restrict__ wo,
                                 const float* __restrict__ w1, const float* __restrict__ w2,
                                 const float* __restrict__ emb,
                                 __nv_bfloat16* __restrict__ qkv_h, __nv_bfloat16* __restrict__ qkv_l,
                                 __nv_bfloat16* __restrict__ wo_h,  __nv_bfloat16* __restrict__ wo_l,
                                 __nv_bfloat16* __restrict__ w1_h,  __nv_bfloat16* __restrict__ w1_l,
                                 __nv_bfloat16* __restrict__ w2_h,  __nv_bfloat16* __restrict__ w2_l,
                                 __nv_bfloat16* __restrict__ emb_h, __nv_bfloat16* __restrict__ emb_l) {
    int i = blockIdx.x * blockDim.x + threadIdx.x;
    if (i >= N_SPLIT_TOT) return;
    if (i < N_QKV) {
        int l = i / (DMOD * QKVN);
        int rem = i % (DMOD * QKVN);
        int k = rem / QKVN, j = rem % QKVN;
        const float* s = (j < DMOD) ? wq : (j < 2 * DMOD) ? wk : wv;
        float v = s[(size_t)l * DMOD * DMOD + (size_t)k * DMOD + (j % DMOD)];
        split2(v, qkv_h[i], qkv_l[i]);
        return;
    }
    i -= N_QKV;
    if (i < N_WO)  { split2(wo[i],  wo_h[i],  wo_l[i]);  return; }
    i -= N_WO;
    if (i < N_W1)  { split2(w1[i],  w1_h[i],  w1_l[i]);  return; }
    i -= N_W1;
    if (i < N_W2)  { split2(w2[i],  w2_h[i],  w2_l[i]);  return; }
    i -= N_W2;
    split2(emb[i], emb_h[i], emb_l[i]);
}

// ---------------- embedding ----------------
__global__ void embed_kernel(const int* __restrict__ ids, const float* __restrict__ emb,
                             const float* __restrict__ pe, float* __restrict__ X) {
    int i = blockIdx.x * blockDim.x + threadIdx.x;
    if (i >= MTOK * DMOD) return;
    int d = i % DMOD, t = i / DMOD, s = t % SEQ;
    X[i] = emb[(size_t)ids[t] * DMOD + d] + pe[s * DMOD + d];
}

// ---------------- layernorm -> bf16 hi/lo ----------------
__global__ void ln_kernel(const float* __restrict__ X, const float* __restrict__ w,
                          const float* __restrict__ bvec,
                          __nv_bfloat16* __restrict__ Yh, __nv_bfloat16* __restrict__ Yl) {
    __shared__ float red[256];
    int row = blockIdx.x, tid = threadIdx.x;
    const float* x = X + (size_t)row * DMOD;
    float s = 0.f;
    for (int i = tid; i < DMOD; i += 256) s += x[i];
    red[tid] = s; __syncthreads();
    for (int o = 128; o > 0; o >>= 1) { if (tid < o) red[tid] += red[tid + o]; __syncthreads(); }
    float mu = red[0] * (1.0f / DMOD); __syncthreads();
    float v = 0.f;
    for (int i = tid; i < DMOD; i += 256) { float t = x[i] - mu; v += t * t; }
    red[tid] = v; __syncthreads();
    for (int o = 128; o > 0; o >>= 1) { if (tid < o) red[tid] += red[tid + o]; __syncthreads(); }
    float rstd = rsqrtf(red[0] * (1.0f / DMOD) + 1e-5f);
    for (int i = tid; i < DMOD; i += 256) {
        float y = (x[i] - mu) * rstd * w[i] + bvec[i];
        __nv_bfloat16 hi, lo; split2(y, hi, lo);
        Yh[(size_t)row * DMOD + i] = hi;
        Yl[(size_t)row * DMOD + i] = lo;
    }
}

// ---------------- GEMM: pre-split bf16, cp.async 2-stage, WMMA 3-term, 2 CTAs/SM ----------------
#define EP_BIAS 1
#define EP_GELU 2
#define EP_RES  4

__device__ __forceinline__ float gelu_exact(float x) {
    return 0.5f * x * (1.0f + erff(x * 0.70710678118654752f));
}

template<int EP, bool BCOL, bool NG, int TN, bool WH>
__global__ void __launch_bounds__(256, 2)
gemm_tc(const __nv_bfloat16* __restrict__ Ah_g, const __nv_bfloat16* __restrict__ Al_g,
        const __nv_bfloat16* __restrict__ Bh_g, const __nv_bfloat16* __restrict__ Bl_g,
        const float* __restrict__ bias, const float* __restrict__ res,
        float* __restrict__ C, __nv_bfloat16* __restrict__ Chi, __nv_bfloat16* __restrict__ Clo,
        int M, int N, int K, int ldb, int ldc) {
    constexpr int ALD = 40;
    constexpr int BLD = BCOL ? 40 : (TN + 8);
    constexpr int ABYTES = 128 * ALD * 2;
    constexpr int BBYTES = BCOL ? (128 * 40 * 2) : (32 * BLD * 2);
    constexpr int STAGEB = 2 * (ABYTES + BBYTES);
    constexpr int NJ = TN / 32;      // j-subtiles per warp

    extern __shared__ char smem[];
    uint32_t sbase = smem_u32(smem);

    int tid = threadIdx.x, lane = tid & 31, wid = tid >> 5;
    int warp_m = wid & 3, warp_n = wid >> 2;
    int bm, bn;
    if (BCOL) { bm = blockIdx.x * 128; bn = blockIdx.y * TN; }   // m fastest -> L2 reuse of B
    else      { bm = blockIdx.y * 128; bn = blockIdx.x * TN; }
    int nch = K >> 5;

    wmma::fragment<wmma::accumulator, 16, 16, 16, float> acc[2][NJ];
    #pragma unroll
    for (int i = 0; i < 2; i++)
        #pragma unroll
        for (int j = 0; j < NJ; j++) wmma::fill_fragment(acc[i][j], 0.f);

    auto load_stage = [&](int s, int c) {
        int k0 = c * 32;
        uint32_t abase = sbase + s * STAGEB;
        #pragma unroll
        for (int hn = 0; hn < 2; hn++) {
            const __nv_bfloat16* g = hn ? Al_g : Ah_g;
            uint32_t db = abase + hn * ABYTES;
            #pragma unroll
            for (int i = 0; i < 2; i++) {
                int cid = tid + i * 256;
                int r = cid >> 2, seg = cid & 3;
                cpa16(db + (uint32_t)(r * ALD + seg * 8) * 2,
                      g + (size_t)(bm + r) * K + k0 + seg * 8);
            }
        }
        uint32_t bbase = abase + 2 * ABYTES;
        if (BCOL) {
            #pragma unroll
            for (int hn = 0; hn < 2; hn++) {
                const __nv_bfloat16* g = hn ? Bl_g : Bh_g;
                uint32_t db = bbase + hn * BBYTES;
                #pragma unroll
                for (int i = 0; i < 2; i++) {
                    int cid = tid + i * 256;
                    int r = cid >> 2, seg = cid & 3;
                    int gn = bn + r;
                    uint32_t d = db + (uint32_t)(r * 40 + seg * 8) * 2;
                    if (!NG || gn < N)
                        cpa16(d, g + (size_t)gn * ldb + k0 + seg * 8);
                    else
                        *reinterpret_cast<uint4*>(smem + (d - sbase)) = make_uint4(0, 0, 0, 0);
                }
            }
        } else {
            constexpr int CH = TN / 8;
            constexpr int NIT = (32 * CH) / 256;
            #pragma unroll
            for (int hn = 0; hn < 2; hn++) {
                const __nv_bfloat16* g = hn ? Bl_g : Bh_g;
                uint32_t db = bbase + hn * BBYTES;
                #pragma unroll
                for (int i = 0; i < NIT; i++) {
                    int cid = tid + i * 256;
                    int kr = cid / CH, seg = cid % CH;
                    cpa16(db + (uint32_t)(kr * BLD + seg * 8) * 2,
                          g + (size_t)(k0 + kr) * ldb + bn + seg * 8);
                }
            }
        }
        CP_COMMIT();
    };

    auto do_mma = [&](int s) {
        char* base = smem + s * STAGEB;
        __nv_bfloat16* Ah = reinterpret_cast<__nv_bfloat16*>(base);
        __nv_bfloat16* Al = reinterpret_cast<__nv_bfloat16*>(base + ABYTES);
        __nv_bfloat16* Bh = reinterpret_cast<__nv_bfloat16*>(base + 2 * ABYTES);
        __nv_bfloat16* Bl = reinterpret_cast<__nv_bfloat16*>(base + 2 * ABYTES + BBYTES);
        #pragma unroll
        for (int kk = 0; kk < 2; kk++) {
            wmma::fragment<wmma::matrix_a, 16, 16, 16, __nv_bfloat16, wmma::row_major> ah[2], al[2];
            #pragma unroll
            for (int i = 0; i < 2; i++) {
                wmma::load_matrix_sync(ah[i], Ah + (warp_m * 32 + i * 16) * ALD + kk * 16, ALD);
                wmma::load_matrix_sync(al[i], Al + (warp_m * 32 + i * 16) * ALD + kk * 16, ALD);
            }
            #pragma unroll
            for (int j = 0; j < NJ; j++) {
                if (BCOL) {
                    wmma::fragment<wmma::matrix_b, 16, 16, 16, __nv_bfloat16, wmma::col_major> bh, bl;
                    wmma::load_matrix_sync(bh, Bh + (warp_n * (TN / 2) + j * 16) * 40 + kk * 16, 40);
                    wmma::load_matrix_sync(bl, Bl + (warp_n * (TN / 2) + j * 16) * 40 + kk * 16, 40);
                    #pragma unroll
                    for (int i = 0; i < 2; i++) {
                        wmma::mma_sync(acc[i][j], ah[i], bh, acc[i][j]);
                        wmma::mma_sync(acc[i][j], ah[i], bl, acc[i][j]);
                        wmma::mma_sync(acc[i][j], al[i], bh, acc[i][j]);
                    }
                } else {
                    wmma::fragment<wmma::matrix_b, 16, 16, 16, __nv_bfloat16, wmma::row_major> bh, bl;
                    wmma::load_matrix_sync(bh, Bh + (kk * 16) * BLD + warp_n * (TN / 2) + j * 16, BLD);
                    wmma::load_matrix_sync(bl, Bl + (kk * 16) * BLD + warp_n * (TN / 2) + j * 16, BLD);
                    #pragma unroll
                    for (int i = 0; i < 2; i++) {
                        wmma::mma_sync(acc[i][j], ah[i], bh, acc[i][j]);
                        wmma::mma_sync(acc[i][j], ah[i], bl, acc[i][j]);
                        wmma::mma_sync(acc[i][j], al[i], bh, acc[i][j]);
                    }
                }
            }
        }
    };

    // 2-stage pipeline with distance-2 prefetch (empty commits keep group counting exact)
    load_stage(0, 0);
    load_stage(1, 1);
    for (int c = 0; c < nch; c++) {
        CP_WAIT1();
        __syncthreads();
        do_mma(c & 1);
        __syncthreads();
        if (c + 2 < nch) load_stage(c & 1, c + 2);
        else CP_COMMIT();
    }

    // epilogue: per-warp smem staging (reuse stage 0)
    float* stg = reinterpret_cast<float*>(smem) + wid * (16 * 20);
    int r = lane >> 1, cb = (lane & 1) * 8;
    #pragma unroll
    for (int i = 0; i < 2; i++) {
        #pragma unroll
        for (int j = 0; j < NJ; j++) {
            wmma::store_matrix_sync(stg, acc[i][j], 20, wmma::mem_row_major);
            __syncwarp();
            int m = bm + warp_m * 32 + i * 16 + r;
            int n0 = bn + warp_n * (TN / 2) + j * 16 + cb;
            #pragma unroll
            for (int q = 0; q < 8; q++) {
                int n = n0 + q;
                float v = stg[r * 20 + cb + q];
                if (EP & EP_BIAS) v += bias[n];
                if (EP & EP_GELU) v = gelu_exact(v);
                if (EP & EP_RES)  v += res[(size_t)m * ldc + n];
                if (!NG || n < N) {
                    if (WH) {
                        __nv_bfloat16 hi, lo; split2(v, hi, lo);
                        Chi[(size_t)m * ldc + n] = hi;
                        Clo[(size_t)m * ldc + n] = lo;
                    } else {
                        C[(size_t)m * ldc + n] = v;
                    }
                }
            }
            __syncwarp();
        }
    }
}

// ---------------- flash-style SIMT attention ----------------
#define APD 68
#define ATT_SMEM ((4*64*APD + 3*64)*4 + 64*4)

__global__ void __launch_bounds__(256)
attn_kernel(const float* __restrict__ QKV, const int* __restrict__ amask,
            __nv_bfloat16* __restrict__ Oh, __nv_bfloat16* __restrict__ Ol) {
    extern __shared__ char asmem[];
    float* Qt = reinterpret_cast<float*>(asmem);            // [d][i]
    float* Kt = Qt + 64 * APD;                              // [d][j]
    float* Vs = Kt + 64 * APD;                              // [j][d]
    float* Pt = Vs + 64 * APD;                              // [j][i]
    float* sm_m = Pt + 64 * APD;
    float* sm_l = sm_m + 64;
    float* sm_s = sm_l + 64;
    int*   msk  = reinterpret_cast<int*>(sm_s + 64);

    int b = blockIdx.z, h = blockIdx.y, qt = blockIdx.x;
    int tid = threadIdx.x;
    int q0 = qt * 64;
    int ty = tid >> 4, tx = tid & 15;

    for (int idx = tid; idx < 64 * 64; idx += 256) {
        int i = idx >> 6, d = idx & 63;
        Qt[d * APD + i] = QKV[(size_t)(b * SEQ + q0 + i) * QKVN + h * DKH + d] * 0.125f;
    }
    if (tid < 64) { sm_m[tid] = -1e30f; sm_l[tid] = 0.f; }

    float o[4][4] = {};
    int ntile = qt + 1;

    for (int kt = 0; kt < ntile; kt++) {
        int k0 = kt * 64;
        __syncthreads();
        for (int idx = tid; idx < 64 * 64; idx += 256) {
            int j = idx >> 6, d = idx & 63;
            Kt[d * APD + j] = QKV[(size_t)(b * SEQ + k0 + j) * QKVN + DMOD + h * DKH + d];
        }
        for (int idx = tid; idx < 64 * 16; idx += 256) {
            int j = idx >> 4, s4 = idx & 15;
            float4 vv = *reinterpret_cast<const float4*>(
                &QKV[(size_t)(b * SEQ + k0 + j) * QKVN + 2 * DMOD + h * DKH + s4 * 4]);
            *reinterpret_cast<float4*>(&Vs[j * APD + s4 * 4]) = vv;
        }
        if (tid < 64) msk[tid] = amask[b * SEQ + k0 + tid];
        __syncthreads();

        float s[4][4] = {};
        for (int d = 0; d < 64; d++) {
            float4 qv = *reinterpret_cast<float4*>(&Qt[d * APD + ty * 4]);
            float4 kv = *reinterpret_cast<float4*>(&Kt[d * APD + tx * 4]);
            float qa[4] = {qv.x, qv.y, qv.z, qv.w};
            float ka[4] = {kv.x, kv.y, kv.z, kv.w};
            #pragma unroll
            for (int rr = 0; rr < 4; rr++)
                #pragma unroll
                for (int cc = 0; cc < 4; cc++) s[rr][cc] += qa[rr] * ka[cc];
        }
        #pragma unroll
        for (int rr = 0; rr < 4; rr++)
            #pragma unroll
            for (int cc = 0; cc < 4; cc++) {
                int i = ty * 4 + rr, j = tx * 4 + cc;
                float v = s[rr][cc];
                if (msk[j] == 0 || (k0 + j) > (q0 + i)) v = -1e9f;
                Pt[j * APD + i] = v;
            }
        __syncthreads();

        {
            int row = tid >> 2, qq = tid & 3;
            float tmax = -1e30f;
            #pragma unroll
            for (int jj = 0; jj < 16; jj++) tmax = fmaxf(tmax, Pt[(qq * 16 + jj) * APD + row]);
            tmax = fmaxf(tmax, __shfl_xor_sync(0xffffffff, tmax, 1));
            tmax = fmaxf(tmax, __shfl_xor_sync(0xffffffff, tmax, 2));
            float mold = sm_m[row];
            float newm = fmaxf(mold, tmax);
            float psum = 0.f;
            #pragma unroll
            for (int jj = 0; jj < 16; jj++) {
                int j = qq * 16 + jj;
                float p = __expf(Pt[j * APD + row] - newm);
                Pt[j * APD + row] = p;
                psum += p;
            }
            psum += __shfl_xor_sync(0xffffffff, psum, 1);
            psum += __shfl_xor_sync(0xffffffff, psum, 2);
            if (qq == 0) {
                float sc = __expf(mold - newm);
                sm_s[row] = sc;
                sm_l[row] = sm_l[row] * sc + psum;
                sm_m[row] = newm;
            }
        }
        __syncthreads();

        {
            float sc[4];
            #pragma unroll
            for (int rr = 0; rr < 4; rr++) sc[rr] = sm_s[ty * 4 + rr];
            #pragma unroll
            for (int rr = 0; rr < 4; rr++)
                #pragma unroll
                for (int cc = 0; cc < 4; cc++) o[rr][cc] *= sc[rr];
            for (int j = 0; j < 64; j++) {
                float4 pv = *reinterpret_cast<float4*>(&Pt[j * APD + ty * 4]);
                float4 vv = *reinterpret_cast<float4*>(&Vs[j * APD + tx * 4]);
                float pa[4] = {pv.x, pv.y, pv.z, pv.w};
                float va[4] = {vv.x, vv.y, vv.z, vv.w};
                #pragma unroll
                for (int rr = 0; rr < 4; rr++)
                    #pragma unroll
                    for (int cc = 0; cc < 4; cc++) o[rr][cc] += pa[rr] * va[cc];
            }
        }
    }
    __syncthreads();
    {
        float inv[4];
        #pragma unroll
        for (int rr = 0; rr < 4; rr++) inv[rr] = 1.0f / sm_l[ty * 4 + rr];
        #pragma unroll
        for (int rr = 0; rr < 4; rr++)
            #pragma unroll
            for (int cc = 0; cc < 4; cc++) {
                size_t off = (size_t)(b * SEQ + q0 + ty * 4 + rr) * DMOD + h * DKH + tx * 4 + cc;
                float v = o[rr][cc] * inv[rr];
                __nv_bfloat16 hi, lo; split2(v, hi, lo);
                Oh[off] = hi; Ol[off] = lo;
            }
    }
}

// ---------------- launch ----------------
extern "C" void kernel_launch(void* const* d_in, const int* in_sizes, int n_in,
                              void* d_out, int out_size) {
    const int*   ids   = (const int*)  d_in[0];
    const int*   amask = (const int*)  d_in[1];
    const float* emb   = (const float*)d_in[2];
    const float* pe    = (const float*)d_in[3];
    const float* wq    = (const float*)d_in[4];
    const float* wk    = (const float*)d_in[5];
    const float* wv    = (const float*)d_in[6];
    const float* wo    = (const float*)d_in[7];
    const float* ln1w  = (const float*)d_in[8];
    const float* ln1b  = (const float*)d_in[9];
    const float* ln2w  = (const float*)d_in[10];
    const float* ln2b  = (const float*)d_in[11];
    const float* w1    = (const float*)d_in[12];
    const float* b1    = (const float*)d_in[13];
    const float* w2    = (const float*)d_in[14];
    const float* b2    = (const float*)d_in[15];
    const float* lnfw  = (const float*)d_in[16];
    const float* lnfb  = (const float*)d_in[17];
    float* out = (float*)d_out;

    float *x, *qkv;
    __nv_bfloat16 *h_h, *h_l, *att_h, *att_l, *ff_h, *ff_l;
    __nv_bfloat16 *wqkv_h, *wqkv_l, *wo_h, *wo_l, *w1_h, *w1_l, *w2_h, *w2_l, *emb_h, *emb_l;
    cudaGetSymbolAddress((void**)&x,     g_x);
    cudaGetSymbolAddress((void**)&qkv,   g_qkv);
    cudaGetSymbolAddress((void**)&h_h,   g_h_h);   cudaGetSymbolAddress((void**)&h_l,   g_h_l);
    cudaGetSymbolAddress((void**)&att_h, g_att_h); cudaGetSymbolAddress((void**)&att_l, g_att_l);
    cudaGetSymbolAddress((void**)&ff_h,  g_ff_h);  cudaGetSymbolAddress((void**)&ff_l,  g_ff_l);
    cudaGetSymbolAddress((void**)&wqkv_h, g_wqkv_h); cudaGetSymbolAddress((void**)&wqkv_l, g_wqkv_l);
    cudaGetSymbolAddress((void**)&wo_h,  g_wo_h);  cudaGetSymbolAddress((void**)&wo_l,  g_wo_l);
    cudaGetSymbolAddress((void**)&w1_h,  g_w1_h);  cudaGetSymbolAddress((void**)&w1_l,  g_w1_l);
    cudaGetSymbolAddress((void**)&w2_h,  g_w2_h);  cudaGetSymbolAddress((void**)&w2_l,  g_w2_l);
    cudaGetSymbolAddress((void**)&emb_h, g_emb_h); cudaGetSymbolAddress((void**)&emb_l, g_emb_l);

    // smem per variant (2-stage)
    const int SM_T128 = 2 * (2 * (128 * 40 * 2) + 2 * (32 * 136 * 2));   // 75776
    const int SM_T64  = 2 * (2 * (128 * 40 * 2) + 2 * (32 * 72 * 2));    // 59392
    const int SM_COL  = 2 * (2 * (128 * 40 * 2) + 2 * (128 * 40 * 2));   // 81920

    cudaFuncSetAttribute(gemm_tc<0, false, false, 128, false>,                cudaFuncAttributeMaxDynamicSharedMemorySize, SM_T128);
    cudaFuncSetAttribute(gemm_tc<EP_RES, false, false, 64, false>,            cudaFuncAttributeMaxDynamicSharedMemorySize, SM_T64);
    cudaFuncSetAttribute(gemm_tc<EP_BIAS | EP_GELU, false, false, 128, true>, cudaFuncAttributeMaxDynamicSharedMemorySize, SM_T128);
    cudaFuncSetAttribute(gemm_tc<EP_BIAS | EP_RES, false, false, 64, false>,  cudaFuncAttributeMaxDynamicSharedMemorySize, SM_T64);
    cudaFuncSetAttribute(gemm_tc<0, true, true, 128, false>,                  cudaFuncAttributeMaxDynamicSharedMemorySize, SM_COL);
    cudaFuncSetAttribute(attn_kernel, cudaFuncAttributeMaxDynamicSharedMemorySize, ATT_SMEM);

    // prepass (1 launch) + embedding
    split_all_kernel<<<(N_SPLIT_TOT + 255) / 256, 256>>>(
        wq, wk, wv, wo, w1, w2, emb,
        wqkv_h, wqkv_l, wo_h, wo_l, w1_h, w1_l, w2_h, w2_l, emb_h, emb_l);
    { int n = MTOK * DMOD; embed_kernel<<<(n + 255) / 256, 256>>>(ids, emb, pe, x); }

    dim3 gQKV(QKVN / 128, MTOK / 128);   // 18 x 16
    dim3 gD64(DMOD / 64, MTOK / 128);    // 12 x 16
    dim3 gF(FFD / 128, MTOK / 128);      // 24 x 16

    for (int l = 0; l < LNUM; l++) {
        ln_kernel<<<MTOK, 256>>>(x, ln1w + l * DMOD, ln1b + l * DMOD, h_h, h_l);

        gemm_tc<0, false, false, 128, false><<<gQKV, 256, SM_T128>>>(
            h_h, h_l, wqkv_h + (size_t)l * DMOD * QKVN, wqkv_l + (size_t)l * DMOD * QKVN,
            nullptr, nullptr, qkv, nullptr, nullptr, MTOK, QKVN, DMOD, QKVN, QKVN);

        attn_kernel<<<dim3(SEQ / 64, HNUM, BAT), 256, ATT_SMEM>>>(qkv, amask, att_h, att_l);

        gemm_tc<EP_RES, false, false, 64, false><<<gD64, 256, SM_T64>>>(
            att_h, att_l, wo_h + (size_t)l * DMOD * DMOD, wo_l + (size_t)l * DMOD * DMOD,
            nullptr, x, x, nullptr, nullptr, MTOK, DMOD, DMOD, DMOD, DMOD);

        ln_kernel<<<MTOK, 256>>>(x, ln2w + l * DMOD, ln2b + l * DMOD, h_h, h_l);

        gemm_tc<EP_BIAS | EP_GELU, false, false, 128, true><<<gF, 256, SM_T128>>>(
            h_h, h_l, w1_h + (size_t)l * DMOD * FFD, w1_l + (size_t)l * DMOD * FFD,
            b1 + (size_t)l * FFD, nullptr, nullptr, ff_h, ff_l, MTOK, FFD, DMOD, FFD, FFD);

        gemm_tc<EP_BIAS | EP_RES, false, false, 64, false><<<gD64, 256, SM_T64>>>(
            ff_h, ff_l, w2_h + (size_t)l * FFD * DMOD, w2_l + (size_t)l * FFD * DMOD,
            b2 + (size_t)l * DMOD, x, x, nullptr, nullptr, MTOK, DMOD, FFD, DMOD, DMOD);
    }

    ln_kernel<<<MTOK, 256>>>(x, lnfw, lnfb, h_h, h_l);

    // lm_head: m-tiles fastest (blockIdx.x) so each wave reuses B slices from L2
    dim3 gV(MTOK / 128, (VOC + 127) / 128);
    gemm_tc<0, true, true, 128, false><<<gV, 256, SM_COL>>>(
        h_h, h_l, emb_h, emb_l, nullptr, nullptr, out, nullptr, nullptr, MTOK, VOC, DMOD, DMOD, VOC);
}